// round 15
// baseline (speedup 1.0000x reference)
#include <cuda_runtime.h>
#include <cuda_bf16.h>
#include <cstdint>

// Problem: e[8192,1024] f32, c[50257,1024] f32, targets[8192] i32 -> scalar f32 mean NLL
#define NTOK 8192
#define DK   1024
#define VV   50257
#define VPAD 50304          // 393 * 128
#define NVT  393            // 128-wide vocab tiles

#define BMC 256             // CTA rows
#define BN  128             // CTA vocab cols
#define BK  64              // bf16 K per stage (128 B rows)
#define NKT (DK / BK)       // 16
#define STAGES 3
#define STAGE_BYTES 49152   // A 32KB + B 16KB
#define DYN_SMEM (STAGES * STAGE_BYTES)   // 144 KB

// -------- scratch (device globals; referenced ONLY from device code) --------
__device__ __align__(16) __nv_bfloat16 g_e16[(size_t)NTOK * DK];   // 16 MB
__device__ __align__(16) __nv_bfloat16 g_c16[(size_t)VPAD * DK];   // ~103 MB (pad rows 0)
__device__ float g_pmax[(size_t)NTOK * NVT];
__device__ float g_psum[(size_t)NTOK * NVT];
__device__ float g_nll[NTOK];

// ---------------- conversion ----------------
__global__ void cce_cvt_e(const float* __restrict__ e) {
    size_t n = (size_t)NTOK * DK;
    for (size_t i = blockIdx.x * (size_t)blockDim.x + threadIdx.x; i < n;
         i += (size_t)gridDim.x * blockDim.x)
        g_e16[i] = __float2bfloat16(e[i]);
}
__global__ void cce_cvt_c(const float* __restrict__ c) {
    size_t n  = (size_t)VPAD * DK;
    size_t nv = (size_t)VV * DK;
    for (size_t i = blockIdx.x * (size_t)blockDim.x + threadIdx.x; i < n;
         i += (size_t)gridDim.x * blockDim.x)
        g_c16[i] = (i < nv) ? __float2bfloat16(c[i]) : __float2bfloat16(0.0f);
}

// ---------------- PTX helpers ----------------
__device__ __forceinline__ uint32_t smem_u32(const void* p) {
    return (uint32_t)__cvta_generic_to_shared(p);
}
__device__ __forceinline__ void cp16(uint32_t s, const void* g) {
    asm volatile("cp.async.cg.shared.global [%0], [%1], 16;" :: "r"(s), "l"(g));
}
#define CP_COMMIT() asm volatile("cp.async.commit_group;" ::: "memory")

#define LDSM_X4(r0, r1, r2, r3, addr)                                            \
    asm volatile("ldmatrix.sync.aligned.m8n8.x4.shared.b16 {%0,%1,%2,%3}, [%4];" \
                 : "=r"(r0), "=r"(r1), "=r"(r2), "=r"(r3) : "r"(addr))

#define MMA_16816(d, a0, a1, a2, a3, b0, b1)                                     \
    asm volatile(                                                                \
        "mma.sync.aligned.m16n8k16.row.col.f32.bf16.bf16.f32 "                   \
        "{%0,%1,%2,%3}, {%4,%5,%6,%7}, {%8,%9}, {%0,%1,%2,%3};"                  \
        : "+f"(d[0]), "+f"(d[1]), "+f"(d[2]), "+f"(d[3])                         \
        : "r"(a0), "r"(a1), "r"(a2), "r"(a3), "r"(b0), "r"(b1))

// ---------------- fused bf16 GEMM + partial LSE ----------------
// grid = (NTOK/BMC, NVT), x fastest (row tiles share each c slice via L2).
// 256 threads = 8 warps as 4x2; warp tile 64x64 (acc 128 regs) to amortize
// LDSM/STS/issue per HMMA. 3-stage cp.async, 128B rows, chunk^=row&7 swizzle.
__global__ void __launch_bounds__(256, 1) cce_gemm_lse() {
    extern __shared__ __align__(128) char dynsm[];
    __shared__ float combM[BMC][2];
    __shared__ float combS[BMC][2];

    const uint32_t sdyn = smem_u32(dynsm);
    const int tid = threadIdx.x, lane = tid & 31, wid = tid >> 5;
    const int wr = wid & 3;   // warp row: 64 rows
    const int wc = wid >> 2;  // warp col: 64 cols
    const int row0 = blockIdx.x * BMC, col0 = blockIdx.y * BN;
    const int vt = blockIdx.y;
    const int gid = lane >> 2, tig = lane & 3;

    // fill stage s with K-chunk kt: A 256x128B (8 cp16/thr) + B 128x128B (4 cp16/thr)
    auto fill = [&](int s, int kt) {
        const uint32_t st = sdyn + (uint32_t)s * STAGE_BYTES;
#pragma unroll
        for (int q = 0; q < 8; q++) {
            int v = tid + q * 256;             // 0..2047
            int r = v >> 3, ch = v & 7;
            uint32_t sw = (uint32_t)(ch ^ (r & 7)) << 4;
            cp16(st + (uint32_t)(r * 128) + sw,
                 g_e16 + (size_t)(row0 + r) * DK + kt * BK + ch * 8);
        }
#pragma unroll
        for (int q = 0; q < 4; q++) {
            int v = tid + q * 256;             // 0..1023
            int r = v >> 3, ch = v & 7;
            uint32_t sw = (uint32_t)(ch ^ (r & 7)) << 4;
            cp16(st + 32768u + (uint32_t)(r * 128) + sw,
                 g_c16 + (size_t)(col0 + r) * DK + kt * BK + ch * 8);
        }
        CP_COMMIT();
    };

    float acc[4][8][4];
#pragma unroll
    for (int i = 0; i < 4; i++)
#pragma unroll
        for (int j = 0; j < 8; j++)
#pragma unroll
            for (int k = 0; k < 4; k++) acc[i][j][k] = 0.0f;

    // ldmatrix addressing (proven mapping): row = base + (lane&15),
    // chunkIdx = 2*ks + (lane>>4), sw = chunkIdx ^ (row&7)
    const int lrow = lane & 15;
    const int csel = lane >> 4;
    const int rAb = wr * 64 + lrow;            // + i*16, i=0..3
    const int rBb = wc * 64 + lrow;            // + t*16, t=0..3
    const int xa = rAb & 7, xb = rBb & 7;

    fill(0, 0);
    fill(1, 1);

#pragma unroll 1
    for (int kt = 0; kt < NKT; kt++) {
        const int s = kt - (kt / STAGES) * STAGES;
        if (kt < NKT - 1) asm volatile("cp.async.wait_group 1;" ::: "memory");
        else              asm volatile("cp.async.wait_group 0;" ::: "memory");
        __syncthreads();
        if (kt + 2 < NKT) fill((kt + 2) - ((kt + 2) / STAGES) * STAGES, kt + 2);

        const uint32_t sAa = sdyn + (uint32_t)s * STAGE_BYTES;
        const uint32_t sBb = sAa + 32768u;
#pragma unroll
        for (int ks = 0; ks < 4; ks++) {       // four k16 slabs of BK=64
            const int cA = 2 * ks + csel;
            uint32_t a[4][4];
#pragma unroll
            for (int i = 0; i < 4; i++)
                LDSM_X4(a[i][0], a[i][1], a[i][2], a[i][3],
                        sAa + (uint32_t)((rAb + i * 16) * 128) +
                            ((uint32_t)(cA ^ xa) << 4));
#pragma unroll
            for (int t = 0; t < 4; t++) {
                uint32_t b0, b1, b2, b3;       // b0:n0-7/klo b1:n8-15/klo b2/b3:khi
                LDSM_X4(b0, b1, b2, b3,
                        sBb + (uint32_t)((rBb + t * 16) * 128) +
                            ((uint32_t)(cA ^ xb) << 4));
#pragma unroll
                for (int i = 0; i < 4; i++) {
                    MMA_16816(acc[i][2 * t + 0], a[i][0], a[i][1], a[i][2], a[i][3], b0, b2);
                    MMA_16816(acc[i][2 * t + 1], a[i][0], a[i][1], a[i][2], a[i][3], b1, b3);
                }
            }
        }
    }

    // ---- register-resident partial softmax ----
    // acc[i][j][k]: rows c0,c1 -> wr*64+i*16+gid ; c2,c3 -> +8
    //              col = wc*64 + j*8 + 2*tig + (k&1)
#pragma unroll
    for (int i = 0; i < 4; i++) {
        float mA = -1e30f, mB = -1e30f;
#pragma unroll
        for (int j = 0; j < 8; j++) {
            mA = fmaxf(mA, fmaxf(acc[i][j][0], acc[i][j][1]));
            mB = fmaxf(mB, fmaxf(acc[i][j][2], acc[i][j][3]));
        }
        float sA = 0.0f, sB = 0.0f;
#pragma unroll
        for (int j = 0; j < 8; j++) {
            sA += __expf(acc[i][j][0] - mA) + __expf(acc[i][j][1] - mA);
            sB += __expf(acc[i][j][2] - mB) + __expf(acc[i][j][3] - mB);
        }
#pragma unroll
        for (int off = 1; off <= 2; off <<= 1) {
            float mo = __shfl_xor_sync(0xffffffffu, mA, off);
            float so = __shfl_xor_sync(0xffffffffu, sA, off);
            float mn = fmaxf(mA, mo);
            sA = sA * __expf(mA - mn) + so * __expf(mo - mn);
            mA = mn;
            mo = __shfl_xor_sync(0xffffffffu, mB, off);
            so = __shfl_xor_sync(0xffffffffu, sB, off);
            mn = fmaxf(mB, mo);
            sB = sB * __expf(mB - mn) + so * __expf(mo - mn);
            mB = mn;
        }
        if (tig == 0) {
            int r = wr * 64 + i * 16 + gid;
            combM[r][wc] = mA;      combS[r][wc] = sA;
            combM[r + 8][wc] = mB;  combS[r + 8][wc] = sB;
        }
    }
    __syncthreads();

    if (tid < BMC) {
        float m0 = combM[tid][0], m1 = combM[tid][1];
        float M  = fmaxf(m0, m1);
        float S  = combS[tid][0] * __expf(m0 - M) + combS[tid][1] * __expf(m1 - M);
        g_pmax[(size_t)(row0 + tid) * NVT + vt] = M;
        g_psum[(size_t)(row0 + tid) * NVT + vt] = S;
    }
}

// ---------------- per-row LSE merge + exact fp32 target logit ----------------
__global__ void cce_row_nll(const float* __restrict__ e, const float* __restrict__ c,
                            const int* __restrict__ tgt) {
    const int gw   = (blockIdx.x * blockDim.x + threadIdx.x) >> 5;
    const int lane = threadIdx.x & 31;
    if (gw >= NTOK) return;
    const int row = gw;

    float M = -1e30f;
    for (int j = lane; j < NVT; j += 32) M = fmaxf(M, g_pmax[(size_t)row * NVT + j]);
#pragma unroll
    for (int o = 16; o; o >>= 1) M = fmaxf(M, __shfl_xor_sync(0xffffffffu, M, o));

    float S = 0.0f;
    for (int j = lane; j < NVT; j += 32)
        S += g_psum[(size_t)row * NVT + j] * __expf(g_pmax[(size_t)row * NVT + j] - M);
#pragma unroll
    for (int o = 16; o; o >>= 1) S += __shfl_xor_sync(0xffffffffu, S, o);

    const float lse = M + logf(S);

    const int t = tgt[row];
    const bool valid = (t != -100);
    const int  st    = valid ? t : 0;
    const float* er = e + (size_t)row * DK;
    const float* cr = c + (size_t)st * DK;
    float dot = 0.0f;
    for (int k = lane; k < DK; k += 32) dot += er[k] * cr[k];
#pragma unroll
    for (int o = 16; o; o >>= 1) dot += __shfl_xor_sync(0xffffffffu, dot, o);

    if (lane == 0) g_nll[row] = valid ? (lse - dot) : 0.0f;
}

// ---------------- final mean ----------------
__global__ void cce_finalize(const int* __restrict__ tgt, float* __restrict__ out) {
    __shared__ float ss[256];
    __shared__ int   sc[256];
    float s = 0.0f;
    int   cnt = 0;
    for (int i = threadIdx.x; i < NTOK; i += 256) {
        s += g_nll[i];
        cnt += (tgt[i] != -100);
    }
    ss[threadIdx.x] = s;
    sc[threadIdx.x] = cnt;
    __syncthreads();
    for (int o = 128; o; o >>= 1) {
        if (threadIdx.x < o) {
            ss[threadIdx.x] += ss[threadIdx.x + o];
            sc[threadIdx.x] += sc[threadIdx.x + o];
        }
        __syncthreads();
    }
    if (threadIdx.x == 0) out[0] = ss[0] / fmaxf((float)sc[0], 1.0f);
}

extern "C" void kernel_launch(void* const* d_in, const int* in_sizes, int n_in,
                              void* d_out, int out_size) {
    const float* e  = (const float*)d_in[0];
    const float* c  = (const float*)d_in[1];
    const int*   tg = (const int*)d_in[2];   // int32 (JAX x64 disabled)
    float*       out = (float*)d_out;

    cudaFuncSetAttribute(cce_gemm_lse, cudaFuncAttributeMaxDynamicSharedMemorySize,
                         DYN_SMEM);

    cce_cvt_e<<<4096, 256>>>(e);
    cce_cvt_c<<<8192, 256>>>(c);

    dim3 grid(NTOK / BMC, NVT);  // x fastest: row tiles share each c slice via L2
    cce_gemm_lse<<<grid, 256, DYN_SMEM>>>();

    cce_row_nll<<<(NTOK * 32) / 256, 256>>>(e, c, tg);
    cce_finalize<<<1, 256>>>(tg, out);
}

// round 16
// speedup vs baseline: 1.3660x; 1.3660x over previous
#include <cuda_runtime.h>
#include <cuda_fp16.h>
#include <cstdint>

// Problem: e[8192,1024] f32, c[50257,1024] f32, targets[8192] i32 -> scalar f32 mean NLL
#define NTOK 8192
#define DK   1024
#define VV   50257
#define VPAD 50304          // 393 * 128
#define NVT  393            // 128-wide vocab tiles

#define BM 128
#define BN 128
#define BK 64               // fp16 K per stage (128 B rows)
#define NKT (DK / BK)       // 16
#define STAGES 4
#define STAGE_BYTES 32768   // A 16KB + B 16KB
#define DYN_SMEM (STAGES * STAGE_BYTES)   // 128 KB

// -------- scratch (device globals; referenced ONLY from device code) --------
__device__ __align__(16) __half g_e16[(size_t)NTOK * DK];   // 16 MB
__device__ __align__(16) __half g_c16[(size_t)VPAD * DK];   // ~103 MB (pad rows 0)
__device__ float g_pmax[(size_t)NTOK * NVT];
__device__ float g_psum[(size_t)NTOK * NVT];
__device__ float g_nll[NTOK];

// ---------------- conversion ----------------
__global__ void cce_cvt_e(const float* __restrict__ e) {
    size_t n = (size_t)NTOK * DK;
    for (size_t i = blockIdx.x * (size_t)blockDim.x + threadIdx.x; i < n;
         i += (size_t)gridDim.x * blockDim.x)
        g_e16[i] = __float2half(e[i]);
}
__global__ void cce_cvt_c(const float* __restrict__ c) {
    size_t n  = (size_t)VPAD * DK;
    size_t nv = (size_t)VV * DK;
    for (size_t i = blockIdx.x * (size_t)blockDim.x + threadIdx.x; i < n;
         i += (size_t)gridDim.x * blockDim.x)
        g_c16[i] = (i < nv) ? __float2half(c[i]) : __float2half(0.0f);
}

// ---------------- PTX helpers ----------------
__device__ __forceinline__ uint32_t smem_u32(const void* p) {
    return (uint32_t)__cvta_generic_to_shared(p);
}
__device__ __forceinline__ void cp16(uint32_t s, const void* g) {
    asm volatile("cp.async.cg.shared.global [%0], [%1], 16;" :: "r"(s), "l"(g));
}
#define CP_COMMIT() asm volatile("cp.async.commit_group;" ::: "memory")

#define LDSM_X4(r0, r1, r2, r3, addr)                                            \
    asm volatile("ldmatrix.sync.aligned.m8n8.x4.shared.b16 {%0,%1,%2,%3}, [%4];" \
                 : "=r"(r0), "=r"(r1), "=r"(r2), "=r"(r3) : "r"(addr))

// fp16 accumulator MMA: d = {d0,d1}, d0 = (c0,c1) rows gid, d1 = (c2,c3) rows gid+8
#define MMA_F16ACC(d, a0, a1, a2, a3, b0, b1)                                    \
    asm volatile(                                                                \
        "mma.sync.aligned.m16n8k16.row.col.f16.f16.f16.f16 "                     \
        "{%0,%1}, {%2,%3,%4,%5}, {%6,%7}, {%0,%1};"                              \
        : "+r"((d)[0]), "+r"((d)[1])                                             \
        : "r"(a0), "r"(a1), "r"(a2), "r"(a3), "r"(b0), "r"(b1))

// ---------------- fused fp16 GEMM (chunked fp16 acc) + partial LSE ----------------
// grid = (NTOK/BM, NVT), x fastest (row tiles share each c slice via L2).
// 256 threads = 8 warps (4 row x 2 col), warp tile 32x64 — proven layout.
// 4-stage cp.async pipeline. fp16 accumulators, promoted to fp32 every 4 K-stages
// (K-chunks of 256) to bound rounding error.
__global__ void __launch_bounds__(256, 1) cce_gemm_lse() {
    extern __shared__ __align__(128) char dynsm[];
    __shared__ float combM[BM][2];
    __shared__ float combS[BM][2];

    const uint32_t sdyn = smem_u32(dynsm);
    const int tid = threadIdx.x, lane = tid & 31, wid = tid >> 5;
    const int wr = wid & 3;   // warp row: 32 rows
    const int wc = wid >> 2;  // warp col: 64 cols
    const int row0 = blockIdx.x * BM, col0 = blockIdx.y * BN;
    const int vt = blockIdx.y;
    const int gid = lane >> 2, tig = lane & 3;

    // fill stage s with K-chunk kt: A and B each 128 rows x 128B, 4 cp16/thread each
    auto fill = [&](int s, int kt) {
        const uint32_t st = sdyn + (uint32_t)s * STAGE_BYTES;
#pragma unroll
        for (int q = 0; q < 4; q++) {
            int v = tid + q * 256;             // 0..1023
            int r = v >> 3, ch = v & 7;
            uint32_t sw = (uint32_t)(ch ^ (r & 7)) << 4;
            cp16(st + (uint32_t)(r * 128) + sw,
                 g_e16 + (size_t)(row0 + r) * DK + kt * BK + ch * 8);
            cp16(st + 16384u + (uint32_t)(r * 128) + sw,
                 g_c16 + (size_t)(col0 + r) * DK + kt * BK + ch * 8);
        }
        CP_COMMIT();
    };

    float acc[2][8][4];                 // fp32 running sums
    uint32_t hacc[2][8][2];             // fp16 chunk accumulators (packed half2)
#pragma unroll
    for (int i = 0; i < 2; i++)
#pragma unroll
        for (int j = 0; j < 8; j++) {
#pragma unroll
            for (int k = 0; k < 4; k++) acc[i][j][k] = 0.0f;
            hacc[i][j][0] = 0u; hacc[i][j][1] = 0u;
        }

    // ldmatrix addressing (proven): row = base + (lane&15),
    // chunkIdx = 2*ks + (lane>>4), sw = chunkIdx ^ (row&7)
    const int lrow = lane & 15;
    const int csel = lane >> 4;
    const int rAb = wr * 32 + lrow;            // + i*16
    const int rBb = wc * 64 + lrow;            // + t*16
    const int xa = rAb & 7, xb = rBb & 7;

    fill(0, 0); fill(1, 1); fill(2, 2);

#pragma unroll 1
    for (int kt = 0; kt < NKT; kt++) {
        const int s = kt & 3;
        // pending before wait = min(kt+3,NKT)-kt; retire chunk kt exactly
        if (kt < NKT - 2)       asm volatile("cp.async.wait_group 2;" ::: "memory");
        else if (kt == NKT - 2) asm volatile("cp.async.wait_group 1;" ::: "memory");
        else                    asm volatile("cp.async.wait_group 0;" ::: "memory");
        __syncthreads();
        if (kt + 3 < NKT) fill((kt + 3) & 3, kt + 3);

        const uint32_t sAa = sdyn + (uint32_t)s * STAGE_BYTES;
        const uint32_t sBb = sAa + 16384u;
#pragma unroll
        for (int ks = 0; ks < 4; ks++) {       // four k16 slabs of BK=64
            const int cA = 2 * ks + csel;
            uint32_t a[2][4];
#pragma unroll
            for (int i = 0; i < 2; i++)
                LDSM_X4(a[i][0], a[i][1], a[i][2], a[i][3],
                        sAa + (uint32_t)((rAb + i * 16) * 128) +
                            ((uint32_t)(cA ^ xa) << 4));
#pragma unroll
            for (int t = 0; t < 4; t++) {
                uint32_t b0, b1, b2, b3;       // b0:n0-7/klo b1:n8-15/klo b2/b3:khi
                LDSM_X4(b0, b1, b2, b3,
                        sBb + (uint32_t)((rBb + t * 16) * 128) +
                            ((uint32_t)(cA ^ xb) << 4));
#pragma unroll
                for (int i = 0; i < 2; i++) {
                    MMA_F16ACC(hacc[i][2 * t + 0], a[i][0], a[i][1], a[i][2], a[i][3], b0, b2);
                    MMA_F16ACC(hacc[i][2 * t + 1], a[i][0], a[i][1], a[i][2], a[i][3], b1, b3);
                }
            }
        }

        // promote fp16 chunk sums to fp32 every 4 K-stages (K-chunk = 256)
        if ((kt & 3) == 3) {
#pragma unroll
            for (int i = 0; i < 2; i++)
#pragma unroll
                for (int j = 0; j < 8; j++) {
                    float2 lo = __half22float2(*(__half2*)&hacc[i][j][0]);
                    float2 hi = __half22float2(*(__half2*)&hacc[i][j][1]);
                    acc[i][j][0] += lo.x; acc[i][j][1] += lo.y;
                    acc[i][j][2] += hi.x; acc[i][j][3] += hi.y;
                    hacc[i][j][0] = 0u;   hacc[i][j][1] = 0u;
                }
        }
    }

    // ---- register-resident partial softmax (proven epilogue) ----
    // acc[i][j][k]: rows c0,c1 -> wr*32+i*16+gid ; c2,c3 -> +8
    //              col = wc*64 + j*8 + 2*tig + (k&1)
#pragma unroll
    for (int i = 0; i < 2; i++) {
        float mA = -1e30f, mB = -1e30f;
#pragma unroll
        for (int j = 0; j < 8; j++) {
            mA = fmaxf(mA, fmaxf(acc[i][j][0], acc[i][j][1]));
            mB = fmaxf(mB, fmaxf(acc[i][j][2], acc[i][j][3]));
        }
        float sA = 0.0f, sB = 0.0f;
#pragma unroll
        for (int j = 0; j < 8; j++) {
            sA += __expf(acc[i][j][0] - mA) + __expf(acc[i][j][1] - mA);
            sB += __expf(acc[i][j][2] - mB) + __expf(acc[i][j][3] - mB);
        }
#pragma unroll
        for (int off = 1; off <= 2; off <<= 1) {
            float mo = __shfl_xor_sync(0xffffffffu, mA, off);
            float so = __shfl_xor_sync(0xffffffffu, sA, off);
            float mn = fmaxf(mA, mo);
            sA = sA * __expf(mA - mn) + so * __expf(mo - mn);
            mA = mn;
            mo = __shfl_xor_sync(0xffffffffu, mB, off);
            so = __shfl_xor_sync(0xffffffffu, sB, off);
            mn = fmaxf(mB, mo);
            sB = sB * __expf(mB - mn) + so * __expf(mo - mn);
            mB = mn;
        }
        if (tig == 0) {
            int r = wr * 32 + i * 16 + gid;
            combM[r][wc] = mA;      combS[r][wc] = sA;
            combM[r + 8][wc] = mB;  combS[r + 8][wc] = sB;
        }
    }
    __syncthreads();

    if (tid < BM) {
        float m0 = combM[tid][0], m1 = combM[tid][1];
        float M  = fmaxf(m0, m1);
        float S  = combS[tid][0] * __expf(m0 - M) + combS[tid][1] * __expf(m1 - M);
        g_pmax[(size_t)(row0 + tid) * NVT + vt] = M;
        g_psum[(size_t)(row0 + tid) * NVT + vt] = S;
    }
}

// ---------------- per-row LSE merge + exact fp32 target logit ----------------
__global__ void cce_row_nll(const float* __restrict__ e, const float* __restrict__ c,
                            const int* __restrict__ tgt) {
    const int gw   = (blockIdx.x * blockDim.x + threadIdx.x) >> 5;
    const int lane = threadIdx.x & 31;
    if (gw >= NTOK) return;
    const int row = gw;

    float M = -1e30f;
    for (int j = lane; j < NVT; j += 32) M = fmaxf(M, g_pmax[(size_t)row * NVT + j]);
#pragma unroll
    for (int o = 16; o; o >>= 1) M = fmaxf(M, __shfl_xor_sync(0xffffffffu, M, o));

    float S = 0.0f;
    for (int j = lane; j < NVT; j += 32)
        S += g_psum[(size_t)row * NVT + j] * __expf(g_pmax[(size_t)row * NVT + j] - M);
#pragma unroll
    for (int o = 16; o; o >>= 1) S += __shfl_xor_sync(0xffffffffu, S, o);

    const float lse = M + logf(S);

    const int t = tgt[row];
    const bool valid = (t != -100);
    const int  st    = valid ? t : 0;
    const float* er = e + (size_t)row * DK;
    const float* cr = c + (size_t)st * DK;
    float dot = 0.0f;
    for (int k = lane; k < DK; k += 32) dot += er[k] * cr[k];
#pragma unroll
    for (int o = 16; o; o >>= 1) dot += __shfl_xor_sync(0xffffffffu, dot, o);

    if (lane == 0) g_nll[row] = valid ? (lse - dot) : 0.0f;
}

// ---------------- final mean ----------------
__global__ void cce_finalize(const int* __restrict__ tgt, float* __restrict__ out) {
    __shared__ float ss[256];
    __shared__ int   sc[256];
    float s = 0.0f;
    int   cnt = 0;
    for (int i = threadIdx.x; i < NTOK; i += 256) {
        s += g_nll[i];
        cnt += (tgt[i] != -100);
    }
    ss[threadIdx.x] = s;
    sc[threadIdx.x] = cnt;
    __syncthreads();
    for (int o = 128; o; o >>= 1) {
        if (threadIdx.x < o) {
            ss[threadIdx.x] += ss[threadIdx.x + o];
            sc[threadIdx.x] += sc[threadIdx.x + o];
        }
        __syncthreads();
    }
    if (threadIdx.x == 0) out[0] = ss[0] / fmaxf((float)sc[0], 1.0f);
}

extern "C" void kernel_launch(void* const* d_in, const int* in_sizes, int n_in,
                              void* d_out, int out_size) {
    const float* e  = (const float*)d_in[0];
    const float* c  = (const float*)d_in[1];
    const int*   tg = (const int*)d_in[2];   // int32 (JAX x64 disabled)
    float*       out = (float*)d_out;

    cudaFuncSetAttribute(cce_gemm_lse, cudaFuncAttributeMaxDynamicSharedMemorySize,
                         DYN_SMEM);

    cce_cvt_e<<<4096, 256>>>(e);
    cce_cvt_c<<<8192, 256>>>(c);

    dim3 grid(NTOK / BM, NVT);  // x fastest: row tiles share each c slice via L2
    cce_gemm_lse<<<grid, 256, DYN_SMEM>>>();

    cce_row_nll<<<(NTOK * 32) / 256, 256>>>(e, c, tg);
    cce_finalize<<<1, 256>>>(tg, out);
}